// round 5
// baseline (speedup 1.0000x reference)
#include <cuda_runtime.h>
#include <cstdint>

// TopKRouter: B=4, T=8192, C=1024, E=8, K=2
//   logits = x @ W^T, softmax, top-2 scatter + indices.
// Proven (rounds 2-4): sequential fp32 FMA over C ascending bit-matches the
// reference logits (output0 rel_err 5.6e-7). Round-4 finding: the harness
// stores BOTH outputs as float32 — top_idx must be written as float values
// (exact-1.0 rel_err under both poison and int32 writes proved the compared
// region reads as ~0 floats).
// Output buffer (fp32): [router_output (262144)] [top_idx-as-float (65536)]

#define ROWS_TOTAL 32768
#define NC4     256                      // float4 per row (C=1024)
#define NE      8
#define WPAD    257                      // padded float4 stride for W in smem
#define OUTP_ELEMS (ROWS_TOTAL * NE)     // 262144

__global__ __launch_bounds__(256, 2)
void router_kernel(const float* __restrict__ x,
                   const float* __restrict__ W,
                   float* __restrict__ out)
{
    // --- stage W (8 x 1024 fp32) into padded smem: ws[e*WPAD + k4] ---
    __shared__ float4 ws[NE * WPAD];
    const float4* w4 = reinterpret_cast<const float4*>(W);
    #pragma unroll
    for (int i = threadIdx.x; i < NE * NC4; i += 256) {
        const int e  = i >> 8;       // i / 256
        const int k4 = i & 255;      // i % 256
        ws[e * WPAD + k4] = w4[i];
    }
    __syncthreads();

    const int lane = threadIdx.x & 31;
    const int warp = threadIdx.x >> 5;
    const int j = lane >> 3;                 // row within warp's 4-row group
    const int e = lane & 7;                  // expert
    const int row = (blockIdx.x * 8 + warp) * 4 + j;

    const float4* x4 = reinterpret_cast<const float4*>(x) + (size_t)row * NC4;
    const float4* wp = ws + e * WPAD;

    // --- strict sequential fp32 FMA accumulation over k ascending ---
    float acc = 0.0f;
    #pragma unroll 8
    for (int k = 0; k < NC4; k++) {
        const float4 xv = __ldg(&x4[k]);     // same addr across the 8 lanes of a row
        const float4 wv = wp[k];             // conflict-free via WPAD padding
        acc = fmaf(xv.x, wv.x, acc);
        acc = fmaf(xv.y, wv.y, acc);
        acc = fmaf(xv.z, wv.z, acc);
        acc = fmaf(xv.w, wv.w, acc);
    }
    const float logit = acc;                 // lane holds logit(row, e) directly

    // --- softmax over the 8-lane expert group (accurate exp, fp32 div) ---
    float mx = logit;
    #pragma unroll
    for (int m = 1; m < 8; m <<= 1)
        mx = fmaxf(mx, __shfl_xor_sync(0xffffffffu, mx, m));
    const float ex = expf(logit - mx);
    float sm = ex;
    #pragma unroll
    for (int m = 1; m < 8; m <<= 1)
        sm += __shfl_xor_sync(0xffffffffu, sm, m);
    const float prob = ex / sm;

    // --- top-1 on probs (tie -> lowest index), all-reduced in the 8-lane group ---
    float bv = prob; int bi = e;
    #pragma unroll
    for (int m = 1; m < 8; m <<= 1) {
        float ov = __shfl_xor_sync(0xffffffffu, bv, m);
        int   oi = __shfl_xor_sync(0xffffffffu, bi, m);
        if (ov > bv || (ov == bv && oi < bi)) { bv = ov; bi = oi; }
    }
    // --- top-2: exclude winner by index (probs > 0, so -1 is a safe sentinel) ---
    float bv2 = (e == bi) ? -1.0f : prob; int bi2 = e;
    #pragma unroll
    for (int m = 1; m < 8; m <<= 1) {
        float ov = __shfl_xor_sync(0xffffffffu, bv2, m);
        int   oi = __shfl_xor_sync(0xffffffffu, bi2, m);
        if (ov > bv2 || (ov == bv2 && oi < bi2)) { bv2 = ov; bi2 = oi; }
    }

    // --- store 0: router_output, one coalesced 128B line per warp ---
    const float o = (e == bi || e == bi2) ? prob : 0.0f;
    out[row * NE + e] = o;

    // --- store 1: top_idx AS FLOAT VALUES (harness output dtype is fp32) ---
    if (e < 2) {
        const int v = (e == 0) ? bi : bi2;   // descending-value order (argmax first)
        out[OUTP_ELEMS + row * 2 + e] = (float)v;
    }
}

extern "C" void kernel_launch(void* const* d_in, const int* in_sizes, int n_in,
                              void* d_out, int out_size)
{
    const float* x = (const float*)d_in[0];
    const float* W = (const float*)d_in[1];
    if (n_in >= 2 && in_sizes[0] < in_sizes[1]) {   // safety: (x, W) order
        x = (const float*)d_in[1];
        W = (const float*)d_in[0];
    }
    // 32768 rows / (4 rows/warp * 8 warps/block) = 1024 blocks
    router_kernel<<<1024, 256>>>(x, W, (float*)d_out);
}